// round 9
// baseline (speedup 1.0000x reference)
#include <cuda_runtime.h>
#include <math.h>

#define MAXN 400000
#define TPB  128

typedef unsigned long long ull;

// Accumulators: [0..3]=S0(k)  [4..15]=S1(k*3+d)  [16..39]=S2(k*6+m)  [40]=loss1  [41]=esum
__device__ double g_acc[42];
__device__ float  g_z[3 * MAXN];          // planar: z1 | cos | euc
__device__ float  g_G[256];               // W3 W3^T  (16x16)
__device__ float  g_w3b[16];              // W3 b
__device__ float  g_bb[1];                // b.b
// GMM params derived once by finalize_kernel
__device__ float  g_mu[12];               // [k][3]
__device__ float  g_si[24];               // [k][6] packed sym inverse
__device__ float  g_c[4];                 // item3 - logphi per k
__device__ float  g_loss3;
__device__ unsigned int g_ticket = 0;

__device__ __forceinline__ ull pk2(float lo, float hi) {
    ull r; asm("mov.b64 %0, {%1, %2};" : "=l"(r) : "f"(lo), "f"(hi)); return r;
}
__device__ __forceinline__ void up2(ull v, float& lo, float& hi) {
    asm("mov.b64 {%0, %1}, %2;" : "=f"(lo), "=f"(hi) : "l"(v));
}
__device__ __forceinline__ ull ffma2(ull a, ull b, ull c) {
    ull d; asm("fma.rn.f32x2 %0, %1, %2, %3;" : "=l"(d) : "l"(a), "l"(b), "l"(c)); return d;
}

__device__ __forceinline__ float tanh_f(float x) {
    float y = fminf(fmaxf(x, -8.f), 8.f);
    float e = __expf(2.f * y);
    return __fdividef(e - 1.f, e + 1.f);
}

__device__ __forceinline__ float wsum(float v) {
#pragma unroll
    for (int o = 16; o; o >>= 1) v += __shfl_down_sync(0xffffffffu, v, o);
    return v;
}

// Precompute G = W3 W3^T, w3b = W3 b, bb = b.b   (dw3: [16][128] row-major)
// Also zeroes accumulators, loss3, ticket.
__global__ void prep_kernel(const float* __restrict__ dw3, const float* __restrict__ db3) {
    int t = threadIdx.x;              // 256 threads
    if (t < 42) g_acc[t] = 0.0;
    if (t == 0) { g_loss3 = 0.f; g_ticket = 0u; }
    int i = t >> 4, j = t & 15;
    float s = 0.f;
#pragma unroll 4
    for (int k = 0; k < 128; k++) s = fmaf(dw3[i * 128 + k], dw3[j * 128 + k], s);
    g_G[t] = s;
    if (t < 16) {
        float w = 0.f;
#pragma unroll 4
        for (int k = 0; k < 128; k++) w = fmaf(dw3[t * 128 + k], db3[k], w);
        g_w3b[t] = w;
    }
    if (t == 0) {
        float b = 0.f;
#pragma unroll 4
        for (int k = 0; k < 128; k++) b = fmaf(db3[k], db3[k], b);
        g_bb[0] = b;
    }
}

__global__ void __launch_bounds__(TPB) fwd_kernel(
    const float* __restrict__ x1,
    const float* __restrict__ ew1, const float* __restrict__ eb1,
    const float* __restrict__ ew2, const float* __restrict__ eb2,
    const float* __restrict__ ew3, const float* __restrict__ eb3,
    const float* __restrict__ dw1, const float* __restrict__ db1,
    const float* __restrict__ dw2, const float* __restrict__ db2,
    const float* __restrict__ dw3, const float* __restrict__ db3,
    const float* __restrict__ tw1, const float* __restrict__ tb1,
    const float* __restrict__ tw2, const float* __restrict__ tb2,
    int n)
{
    // combined weights: sWC[col][0..15]=enc_w1 row col ; sWC[col][16..31]=dw3[:,col]
    __shared__ __align__(16) float sWC[128 * 32];
    __shared__ __align__(16) float sG[256];
    __shared__ __align__(16) float sW3B[16];
    __shared__ __align__(16) float sB1[16];
    __shared__ __align__(16) float sW2[128];
    __shared__ __align__(16) float sB2[8];
    __shared__ __align__(16) float sW3[8];
    __shared__ __align__(16) float sDW1[8];
    __shared__ __align__(16) float sDB1[8];
    __shared__ __align__(16) float sDW2[128];
    __shared__ __align__(16) float sDB2[16];
    __shared__ __align__(16) float sDB3[128];
    __shared__ __align__(16) float sTW1[24];
    __shared__ __align__(16) float sTB1[8];
    __shared__ __align__(16) float sTW2[32];
    __shared__ __align__(16) float sTB2[4];
    __shared__ float sB3, sBB;
    __shared__ float sRed[4][41];

    const int tid = threadIdx.x;

    // -------- stage weights --------
    for (int i = tid; i < 2048; i += TPB) { int c = i >> 4, o = i & 15; sWC[c * 32 + o] = ew1[i]; }
    for (int i = tid; i < 2048; i += TPB) { int r = i >> 7, c = i & 127; sWC[c * 32 + 16 + r] = dw3[i]; }
    for (int i = tid; i < 256; i += TPB) sG[i] = g_G[i];
    for (int i = tid; i < 128; i += TPB) { sW2[i] = ew2[i]; sDW2[i] = dw2[i]; sDB3[i] = db3[i]; }
    if (tid < 16) { sB1[tid] = eb1[tid]; sDB2[tid] = db2[tid]; sW3B[tid] = g_w3b[tid]; }
    if (tid < 8)  { sB2[tid] = eb2[tid]; sW3[tid] = ew3[tid]; sDW1[tid] = dw1[tid]; sDB1[tid] = db1[tid]; sTB1[tid] = tb1[tid]; }
    if (tid < 24) sTW1[tid] = tw1[tid];
    if (tid < 32) sTW2[tid] = tw2[tid];
    if (tid < 4)  sTB2[tid] = tb2[tid];
    if (tid == 0) { sB3 = eb3[0]; sBB = g_bb[0]; }
    __syncthreads();

    const int row = blockIdx.x * TPB + tid;
    const float validf = (row < n) ? 1.f : 0.f;
    const int rr = (row < n) ? row : 0;
    const float4* xp = (const float4*)(x1 + (size_t)rr * 128);

    // ---------------- single pass over x, f32x2-packed accumulators ----------------
    // acc2[0..7]  = enc1 pre-activations (16 floats, paired)
    // acc2[8..15] = u = W3 x            (16 floats, paired)
    ull acc2[16];
#pragma unroll
    for (int q = 0; q < 8; q++) acc2[q] = pk2(sB1[2 * q], sB1[2 * q + 1]);
#pragma unroll
    for (int q = 8; q < 16; q++) acc2[q] = 0ull;
    ull n1p = 0ull, bxp = 0ull;

#pragma unroll 2
    for (int c = 0; c < 32; c++) {
        float4 v = xp[c];
        ull vxy = pk2(v.x, v.y), vzw = pk2(v.z, v.w);
        n1p = ffma2(vxy, vxy, n1p);
        n1p = ffma2(vzw, vzw, n1p);
        const ull* dbp = (const ull*)&sDB3[c * 4];
        bxp = ffma2(vxy, dbp[0], bxp);
        bxp = ffma2(vzw, dbp[1], bxp);
#pragma unroll
        for (int r = 0; r < 4; r++) {
            const int col = c * 4 + r;
            float xv = (r == 0) ? v.x : (r == 1) ? v.y : (r == 2) ? v.z : v.w;
            ull xv2 = pk2(xv, xv);
            const ull* w = (const ull*)&sWC[col * 32];   // 16 packed pairs
#pragma unroll
            for (int q = 0; q < 16; q++) acc2[q] = ffma2(xv2, w[q], acc2[q]);
        }
    }

    float n1, bx;
    { float a, b; up2(n1p, a, b); n1 = a + b; up2(bxp, a, b); bx = a + b; }

    float h1[16];
#pragma unroll
    for (int q = 0; q < 8; q++) {
        float a, b; up2(acc2[q], a, b);
        h1[2 * q] = tanh_f(a); h1[2 * q + 1] = tanh_f(b);
    }

    // ---------------- encoder layer 2 (16->8) ----------------
    float h2[8];
#pragma unroll
    for (int j = 0; j < 8; j++) {
        float t = sB2[j];
#pragma unroll
        for (int i = 0; i < 16; i++) t = fmaf(h1[i], sW2[i * 8 + j], t);
        h2[j] = tanh_f(t);
    }

    // ---------------- encoder layer 3 (8->1) ----------------
    float z1v;
    {
        float t = sB3;
#pragma unroll
        for (int i = 0; i < 8; i++) t = fmaf(h2[i], sW3[i], t);
        z1v = tanh_f(t);
    }

    // ---------------- decoder layer 1 (1->8) ----------------
    float d1[8];
#pragma unroll
    for (int j = 0; j < 8; j++) d1[j] = tanh_f(fmaf(z1v, sDW1[j], sDB1[j]));

    // ---------------- decoder layer 2 (8->16) ----------------
    float d2[16];
#pragma unroll
    for (int j = 0; j < 16; j++) {
        float t = sDB2[j];
#pragma unroll
        for (int i = 0; i < 8; i++) t = fmaf(d1[i], sDW2[i * 16 + j], t);
        d2[j] = tanh_f(t);
    }
    ull d2p[8];
#pragma unroll
    for (int q = 0; q < 8; q++) d2p[q] = pk2(d2[2 * q], d2[2 * q + 1]);

    // ---------------- distances via precomputed Gram (f32x2) ----------------
    // dot(x,x2) = d2.u + b.x ;  ||x2||^2 = d2'G d2 + 2 d2.w3b + bb ;  e2 = n1 - 2dot + n2
    ull dvp = 0ull;
#pragma unroll
    for (int q = 0; q < 8; q++) dvp = ffma2(d2p[q], acc2[8 + q], dvp);
    float dotv;
    { float a, b; up2(dvp, a, b); dotv = bx + a + b; }

    float n2 = sBB;
#pragma unroll
    for (int i = 0; i < 16; i++) {
        const ull* Grow = (const ull*)&sG[i * 16];
        ull gp = 0ull;
#pragma unroll
        for (int q = 0; q < 8; q++) gp = ffma2(Grow[q], d2p[q], gp);
        float a, b; up2(gp, a, b);
        float gi = 2.f * sW3B[i] + a + b;
        n2 = fmaf(d2[i], gi, n2);
    }
    float e2 = fmaxf(n1 - 2.f * dotv + n2, 0.f);

    float prod = sqrtf(n1) * sqrtf(n2);
    float cd = __fdividef(dotv, prod);
    float ed = sqrtf(e2);

    // ---------------- estimator + softmax ----------------
    float eh[8];
#pragma unroll
    for (int j = 0; j < 8; j++) {
        float t = sTB1[j];
        t = fmaf(z1v, sTW1[j],      t);
        t = fmaf(cd,  sTW1[8 + j],  t);
        t = fmaf(ed,  sTW1[16 + j], t);
        eh[j] = tanh_f(t);
    }
    float lg[4];
#pragma unroll
    for (int k = 0; k < 4; k++) {
        float t = sTB2[k];
#pragma unroll
        for (int i = 0; i < 8; i++) t = fmaf(eh[i], sTW2[i * 4 + k], t);
        lg[k] = t;
    }
    float m = fmaxf(fmaxf(lg[0], lg[1]), fmaxf(lg[2], lg[3]));
    float es[4], ssum = 0.f;
#pragma unroll
    for (int k = 0; k < 4; k++) { es[k] = __expf(lg[k] - m); ssum += es[k]; }
    float inv = __fdividef(validf, ssum);          // folds validity into gamma
    float gam[4];
#pragma unroll
    for (int k = 0; k < 4; k++) gam[k] = es[k] * inv;

    if (row < n) {                                 // coalesced stores
        g_z[row]            = z1v;
        g_z[MAXN + row]     = cd;
        g_z[2 * MAXN + row] = ed;
    }

    // ---------------- moments: warp reduce -> block reduce -> atomics ----------------
    float vals[41];
    {
        float p00 = z1v * z1v, p01 = z1v * cd, p02 = z1v * ed;
        float p11 = cd * cd,   p12 = cd * ed,  p22 = ed * ed;
        vals[40] = e2 * validf;
#pragma unroll
        for (int k = 0; k < 4; k++) {
            float gk = gam[k];
            vals[k]              = gk;
            vals[4 + k * 3 + 0]  = gk * z1v;
            vals[4 + k * 3 + 1]  = gk * cd;
            vals[4 + k * 3 + 2]  = gk * ed;
            vals[16 + k * 6 + 0] = gk * p00;
            vals[16 + k * 6 + 1] = gk * p01;
            vals[16 + k * 6 + 2] = gk * p02;
            vals[16 + k * 6 + 3] = gk * p11;
            vals[16 + k * 6 + 4] = gk * p12;
            vals[16 + k * 6 + 5] = gk * p22;
        }
    }
    const int wid = tid >> 5, lane = tid & 31;
#pragma unroll
    for (int q = 0; q < 41; q++) {
        float r = wsum(vals[q]);
        if (lane == 0) sRed[wid][q] = r;
    }
    __syncthreads();
    if (tid < 41) {
        float r = sRed[0][tid] + sRed[1][tid] + sRed[2][tid] + sRed[3][tid];
        atomicAdd(&g_acc[tid], (double)r);
    }
}

// Derive GMM parameters ONCE (k-parallel; moments divided in double, rest in float)
__global__ void finalize_kernel(int n) {
    int k = threadIdx.x;
    if (k < 4) {
        double gs = g_acc[k];
        double m0 = g_acc[4 + k * 3 + 0] / gs;
        double m1 = g_acc[4 + k * 3 + 1] / gs;
        double m2 = g_acc[4 + k * 3 + 2] / gs;
        float a = (float)(g_acc[16 + k * 6 + 0] / gs - m0 * m0);
        float b = (float)(g_acc[16 + k * 6 + 1] / gs - m0 * m1);
        float c = (float)(g_acc[16 + k * 6 + 2] / gs - m0 * m2);
        float d = (float)(g_acc[16 + k * 6 + 3] / gs - m1 * m1);
        float e = (float)(g_acc[16 + k * 6 + 4] / gs - m1 * m2);
        float f = (float)(g_acc[16 + k * 6 + 5] / gs - m2 * m2);
        float det = a * (d * f - e * e) - b * (b * f - c * e) + c * (b * e - c * d);
        float id = __fdividef(1.f, det);
        g_si[k * 6 + 0] = (d * f - e * e) * id;
        g_si[k * 6 + 1] = (c * e - b * f) * id;
        g_si[k * 6 + 2] = (b * e - c * d) * id;
        g_si[k * 6 + 3] = (a * f - c * c) * id;
        g_si[k * 6 + 4] = (b * c - a * e) * id;
        g_si[k * 6 + 5] = (a * d - b * b) * id;
        g_mu[k * 3 + 0] = (float)m0;
        g_mu[k * 3 + 1] = (float)m1;
        g_mu[k * 3 + 2] = (float)m2;
        const float TWO_PI3 = 248.05021344239853f;   // (2*pi)^3
        float phi = (float)(gs / (double)n);
        g_c[k] = 0.5f * logf(TWO_PI3 * det) - logf(phi);
        float l3 = __fdividef(1.f, a) + __fdividef(1.f, d) + __fdividef(1.f, f);
        atomicAdd(&g_loss3, 1e-4f * l3);
    }
}

// energy + (last block) loss
__global__ void __launch_bounds__(256) energy_kernel(float* __restrict__ out, int n, int has_loss) {
    __shared__ float sE[8];
    const int tid = threadIdx.x;

    float mu[12], si[24], cc[4];
#pragma unroll
    for (int q = 0; q < 12; q++) mu[q] = g_mu[q];
#pragma unroll
    for (int q = 0; q < 24; q++) si[q] = g_si[q];
#pragma unroll
    for (int q = 0; q < 4; q++)  cc[q] = g_c[q];

    int i = blockIdx.x * blockDim.x + tid;
    bool v = i < n;
    int ii = v ? i : 0;
    float z0 = g_z[ii], zc = g_z[MAXN + ii], ze = g_z[2 * MAXN + ii];
    float en = 0.f;
#pragma unroll
    for (int k = 0; k < 4; k++) {
        float a = z0 - mu[k * 3 + 0];
        float b = zc - mu[k * 3 + 1];
        float c = ze - mu[k * 3 + 2];
        float q = si[k * 6 + 0] * a * a + si[k * 6 + 3] * b * b + si[k * 6 + 5] * c * c
                + 2.f * (si[k * 6 + 1] * a * b + si[k * 6 + 2] * a * c + si[k * 6 + 4] * b * c);
        en += cc[k] + 0.5f * q;
    }
    if (v) out[i] = en;

    float r = wsum(v ? en : 0.f);
    const int wid = tid >> 5, lane = tid & 31;
    if (lane == 0) sE[wid] = r;
    __syncthreads();
    if (tid == 0) {
        float t = 0.f;
#pragma unroll
        for (int w = 0; w < 8; w++) t += sE[w];
        atomicAdd(&g_acc[41], (double)t);
        __threadfence();
        unsigned int old = atomicInc(&g_ticket, gridDim.x - 1);   // self-resetting
        if (old == gridDim.x - 1) {                                // last block
            __threadfence();
            if (has_loss) {
                double loss = g_acc[40] / (double)n + 0.01 * (g_acc[41] / (double)n)
                            + (double)g_loss3;
                out[n] = (float)loss;
            }
        }
    }
}

extern "C" void kernel_launch(void* const* d_in, const int* in_sizes, int n_in,
                              void* d_out, int out_size) {
    const float* x1  = (const float*)d_in[0];
    const float* ew1 = (const float*)d_in[1];
    const float* eb1 = (const float*)d_in[2];
    const float* ew2 = (const float*)d_in[3];
    const float* eb2 = (const float*)d_in[4];
    const float* ew3 = (const float*)d_in[5];
    const float* eb3 = (const float*)d_in[6];
    const float* dw1 = (const float*)d_in[7];
    const float* db1 = (const float*)d_in[8];
    const float* dw2 = (const float*)d_in[9];
    const float* db2 = (const float*)d_in[10];
    const float* dw3 = (const float*)d_in[11];
    const float* db3 = (const float*)d_in[12];
    const float* tw1 = (const float*)d_in[13];
    const float* tb1 = (const float*)d_in[14];
    const float* tw2 = (const float*)d_in[15];
    const float* tb2 = (const float*)d_in[16];

    int n = in_sizes[0] / 128;
    if (n > MAXN) n = MAXN;
    float* out = (float*)d_out;

    prep_kernel<<<1, 256>>>(dw3, db3);     // zeroes g_acc/g_loss3/g_ticket too
    int blocks = (n + TPB - 1) / TPB;
    fwd_kernel<<<blocks, TPB>>>(x1, ew1, eb1, ew2, eb2, ew3, eb3,
                                dw1, db1, dw2, db2, dw3, db3,
                                tw1, tb1, tw2, tb2, n);
    finalize_kernel<<<1, 32>>>(n);
    energy_kernel<<<(n + 255) / 256, 256>>>(out, n, out_size > n ? 1 : 0);
}

// round 13
// speedup vs baseline: 1.0473x; 1.0473x over previous
#include <cuda_runtime.h>
#include <math.h>
#include <stdint.h>

#define MAXN 400000
#define TPB  128
#define CHUNK 16            // floats per sample staged per chunk
#define NCHUNK 8            // 8 * 16 = 128 floats
#define ROWP 20             // padded row stride in staging buffer (floats, 16B-aligned)
#define BUFF (TPB * ROWP)   // floats per buffer

typedef unsigned long long ull;

// Accumulators: [0..3]=S0(k)  [4..15]=S1(k*3+d)  [16..39]=S2(k*6+m)  [40]=loss1  [41]=esum
__device__ double g_acc[42];
__device__ float  g_z[3 * MAXN];          // planar: z1 | cos | euc
__device__ float  g_G[256];               // W3 W3^T  (16x16)
__device__ float  g_w3b[16];              // W3 b
__device__ float  g_bb[1];                // b.b
__device__ float  g_mu[12];
__device__ float  g_si[24];
__device__ float  g_c[4];
__device__ float  g_loss3;
__device__ unsigned int g_ticket = 0;

__device__ __forceinline__ ull pk2(float lo, float hi) {
    ull r; asm("mov.b64 %0, {%1, %2};" : "=l"(r) : "f"(lo), "f"(hi)); return r;
}
__device__ __forceinline__ void up2(ull v, float& lo, float& hi) {
    asm("mov.b64 {%0, %1}, %2;" : "=f"(lo), "=f"(hi) : "l"(v));
}
__device__ __forceinline__ ull ffma2(ull a, ull b, ull c) {
    ull d; asm("fma.rn.f32x2 %0, %1, %2, %3;" : "=l"(d) : "l"(a), "l"(b), "l"(c)); return d;
}
__device__ __forceinline__ void cp16(unsigned int dst, const float* src) {
    asm volatile("cp.async.ca.shared.global [%0], [%1], 16;" :: "r"(dst), "l"(src));
}

__device__ __forceinline__ float tanh_f(float x) {
    float y = fminf(fmaxf(x, -8.f), 8.f);
    float e = __expf(2.f * y);
    return __fdividef(e - 1.f, e + 1.f);
}

__device__ __forceinline__ float wsum(float v) {
#pragma unroll
    for (int o = 16; o; o >>= 1) v += __shfl_down_sync(0xffffffffu, v, o);
    return v;
}

// Precompute G = W3 W3^T, w3b = W3 b, bb = b.b ; zero accumulators/ticket.
__global__ void prep_kernel(const float* __restrict__ dw3, const float* __restrict__ db3) {
    int t = threadIdx.x;              // 256 threads
    if (t < 42) g_acc[t] = 0.0;
    if (t == 0) { g_loss3 = 0.f; g_ticket = 0u; }
    int i = t >> 4, j = t & 15;
    float s = 0.f;
#pragma unroll 4
    for (int k = 0; k < 128; k++) s = fmaf(dw3[i * 128 + k], dw3[j * 128 + k], s);
    g_G[t] = s;
    if (t < 16) {
        float w = 0.f;
#pragma unroll 4
        for (int k = 0; k < 128; k++) w = fmaf(dw3[t * 128 + k], db3[k], w);
        g_w3b[t] = w;
    }
    if (t == 0) {
        float b = 0.f;
#pragma unroll 4
        for (int k = 0; k < 128; k++) b = fmaf(db3[k], db3[k], b);
        g_bb[0] = b;
    }
}

__global__ void __launch_bounds__(TPB) fwd_kernel(
    const float* __restrict__ x1,
    const float* __restrict__ ew1, const float* __restrict__ eb1,
    const float* __restrict__ ew2, const float* __restrict__ eb2,
    const float* __restrict__ ew3, const float* __restrict__ eb3,
    const float* __restrict__ dw1, const float* __restrict__ db1,
    const float* __restrict__ dw2, const float* __restrict__ db2,
    const float* __restrict__ dw3, const float* __restrict__ db3,
    const float* __restrict__ tw1, const float* __restrict__ tb1,
    const float* __restrict__ tw2, const float* __restrict__ tb2,
    int n)
{
    extern __shared__ __align__(16) float xs[];   // 2 * BUFF floats (double buffer)

    __shared__ __align__(16) float sWC[128 * 32]; // [col][0..15]=ew1 row col ; [16..31]=dw3[:,col]
    __shared__ __align__(16) float sG[256];
    __shared__ __align__(16) float sW3B[16];
    __shared__ __align__(16) float sB1[16];
    __shared__ __align__(16) float sW2[128];
    __shared__ __align__(16) float sB2[8];
    __shared__ __align__(16) float sW3[8];
    __shared__ __align__(16) float sDW1[8];
    __shared__ __align__(16) float sDB1[8];
    __shared__ __align__(16) float sDW2[128];
    __shared__ __align__(16) float sDB2[16];
    __shared__ __align__(16) float sDB3[128];
    __shared__ __align__(16) float sTW1[24];
    __shared__ __align__(16) float sTB1[8];
    __shared__ __align__(16) float sTW2[32];
    __shared__ __align__(16) float sTB2[4];
    __shared__ float sB3, sBB;
    __shared__ float sRed[4][41];

    const int tid = threadIdx.x;
    const int row0 = blockIdx.x * TPB;

    // -------- kick off chunk 0 staging immediately (before weight staging) --------
    const unsigned int xs_base = (unsigned int)__cvta_generic_to_shared(xs);
#pragma unroll
    for (int p = 0; p < 4; p++) {
        int i = tid + p * TPB;
        int s = i >> 2, q = i & 3;
        int gr = row0 + s; if (gr >= n) gr = 0;
        cp16(xs_base + (unsigned int)(s * ROWP + q * 4) * 4u,
             x1 + (size_t)gr * 128 + 0 * CHUNK + q * 4);
    }
    asm volatile("cp.async.commit_group;");

    // -------- stage weights --------
    for (int i = tid; i < 2048; i += TPB) { int c = i >> 4, o = i & 15; sWC[c * 32 + o] = ew1[i]; }
    for (int i = tid; i < 2048; i += TPB) { int r = i >> 7, c = i & 127; sWC[c * 32 + 16 + r] = dw3[i]; }
    for (int i = tid; i < 256; i += TPB) sG[i] = g_G[i];
    for (int i = tid; i < 128; i += TPB) { sW2[i] = ew2[i]; sDW2[i] = dw2[i]; sDB3[i] = db3[i]; }
    if (tid < 16) { sB1[tid] = eb1[tid]; sDB2[tid] = db2[tid]; sW3B[tid] = g_w3b[tid]; }
    if (tid < 8)  { sB2[tid] = eb2[tid]; sW3[tid] = ew3[tid]; sDW1[tid] = dw1[tid]; sDB1[tid] = db1[tid]; sTB1[tid] = tb1[tid]; }
    if (tid < 24) sTW1[tid] = tw1[tid];
    if (tid < 32) sTW2[tid] = tw2[tid];
    if (tid < 4)  sTB2[tid] = tb2[tid];
    if (tid == 0) { sB3 = eb3[0]; sBB = g_bb[0]; }
    __syncthreads();

    const int row = row0 + tid;
    const float validf = (row < n) ? 1.f : 0.f;

    // ---------------- packed accumulators ----------------
    // acc2[0..7]  = enc1 pre-activations (16 floats, paired)
    // acc2[8..15] = u = W3 x            (16 floats, paired)
    ull acc2[16];
#pragma unroll
    for (int q = 0; q < 8; q++) acc2[q] = pk2(sB1[2 * q], sB1[2 * q + 1]);
#pragma unroll
    for (int q = 8; q < 16; q++) acc2[q] = 0ull;
    ull n1p = 0ull, bxp = 0ull;

    // ---------------- chunked x sweep with cp.async double buffer ----------------
#pragma unroll 2
    for (int k = 0; k < NCHUNK; k++) {
        // stage chunk k+1 into the other buffer (its last reader finished at the
        // end-of-iteration barrier of iter k-1)
        if (k < NCHUNK - 1) {
            const unsigned int dstb = xs_base + (unsigned int)(((k + 1) & 1) * BUFF) * 4u;
#pragma unroll
            for (int p = 0; p < 4; p++) {
                int i = tid + p * TPB;
                int s = i >> 2, q = i & 3;
                int gr = row0 + s; if (gr >= n) gr = 0;
                cp16(dstb + (unsigned int)(s * ROWP + q * 4) * 4u,
                     x1 + (size_t)gr * 128 + (k + 1) * CHUNK + q * 4);
            }
            asm volatile("cp.async.commit_group;");
            asm volatile("cp.async.wait_group 1;");
        } else {
            asm volatile("cp.async.wait_group 0;");
        }
        __syncthreads();

        const float* xrow = &xs[(k & 1) * BUFF + tid * ROWP];
#pragma unroll
        for (int j = 0; j < 4; j++) {
            float4 v = *(const float4*)&xrow[j * 4];
            ull vxy = pk2(v.x, v.y), vzw = pk2(v.z, v.w);
            n1p = ffma2(vxy, vxy, n1p);
            n1p = ffma2(vzw, vzw, n1p);
            const int c = k * 4 + j;
            const ull* dbp = (const ull*)&sDB3[c * 4];
            bxp = ffma2(vxy, dbp[0], bxp);
            bxp = ffma2(vzw, dbp[1], bxp);
#pragma unroll
            for (int r = 0; r < 4; r++) {
                const int col = c * 4 + r;
                float xv = (r == 0) ? v.x : (r == 1) ? v.y : (r == 2) ? v.z : v.w;
                ull xv2 = pk2(xv, xv);
                const float4* wp = (const float4*)&sWC[col * 32];
#pragma unroll
                for (int q = 0; q < 8; q++) {
                    float4 wq = wp[q];                   // LDS.128 broadcast
                    ull wlo = pk2(wq.x, wq.y);           // register-pair alias
                    ull whi = pk2(wq.z, wq.w);
                    acc2[2 * q]     = ffma2(xv2, wlo, acc2[2 * q]);
                    acc2[2 * q + 1] = ffma2(xv2, whi, acc2[2 * q + 1]);
                }
            }
        }
        __syncthreads();   // all readers of this buffer done before it is re-staged
    }

    float n1, bx;
    { float a, b; up2(n1p, a, b); n1 = a + b; up2(bxp, a, b); bx = a + b; }

    float h1[16];
#pragma unroll
    for (int q = 0; q < 8; q++) {
        float a, b; up2(acc2[q], a, b);
        h1[2 * q] = tanh_f(a); h1[2 * q + 1] = tanh_f(b);
    }

    // ---------------- encoder layer 2 (16->8) ----------------
    float h2[8];
#pragma unroll
    for (int j = 0; j < 8; j++) {
        float t = sB2[j];
#pragma unroll
        for (int i = 0; i < 16; i++) t = fmaf(h1[i], sW2[i * 8 + j], t);
        h2[j] = tanh_f(t);
    }

    // ---------------- encoder layer 3 (8->1) ----------------
    float z1v;
    {
        float t = sB3;
#pragma unroll
        for (int i = 0; i < 8; i++) t = fmaf(h2[i], sW3[i], t);
        z1v = tanh_f(t);
    }

    // ---------------- decoder layer 1 (1->8) ----------------
    float d1[8];
#pragma unroll
    for (int j = 0; j < 8; j++) d1[j] = tanh_f(fmaf(z1v, sDW1[j], sDB1[j]));

    // ---------------- decoder layer 2 (8->16) ----------------
    float d2[16];
#pragma unroll
    for (int j = 0; j < 16; j++) {
        float t = sDB2[j];
#pragma unroll
        for (int i = 0; i < 8; i++) t = fmaf(d1[i], sDW2[i * 16 + j], t);
        d2[j] = tanh_f(t);
    }
    ull d2p[8];
#pragma unroll
    for (int q = 0; q < 8; q++) d2p[q] = pk2(d2[2 * q], d2[2 * q + 1]);

    // ---------------- distances via precomputed Gram ----------------
    ull dvp = 0ull;
#pragma unroll
    for (int q = 0; q < 8; q++) dvp = ffma2(d2p[q], acc2[8 + q], dvp);
    float dotv;
    { float a, b; up2(dvp, a, b); dotv = bx + a + b; }

    float n2 = sBB;
#pragma unroll
    for (int i = 0; i < 16; i++) {
        const float4* Grow = (const float4*)&sG[i * 16];
        ull gp = 0ull;
#pragma unroll
        for (int q = 0; q < 4; q++) {
            float4 gq = Grow[q];
            gp = ffma2(pk2(gq.x, gq.y), d2p[2 * q], gp);
            gp = ffma2(pk2(gq.z, gq.w), d2p[2 * q + 1], gp);
        }
        float a, b; up2(gp, a, b);
        float gi = 2.f * sW3B[i] + a + b;
        n2 = fmaf(d2[i], gi, n2);
    }
    float e2 = fmaxf(n1 - 2.f * dotv + n2, 0.f);

    float prod = sqrtf(n1) * sqrtf(n2);
    float cd = __fdividef(dotv, prod);
    float ed = sqrtf(e2);

    // ---------------- estimator + softmax ----------------
    float eh[8];
#pragma unroll
    for (int j = 0; j < 8; j++) {
        float t = sTB1[j];
        t = fmaf(z1v, sTW1[j],      t);
        t = fmaf(cd,  sTW1[8 + j],  t);
        t = fmaf(ed,  sTW1[16 + j], t);
        eh[j] = tanh_f(t);
    }
    float lg[4];
#pragma unroll
    for (int k = 0; k < 4; k++) {
        float t = sTB2[k];
#pragma unroll
        for (int i = 0; i < 8; i++) t = fmaf(eh[i], sTW2[i * 4 + k], t);
        lg[k] = t;
    }
    float m = fmaxf(fmaxf(lg[0], lg[1]), fmaxf(lg[2], lg[3]));
    float es[4], ssum = 0.f;
#pragma unroll
    for (int k = 0; k < 4; k++) { es[k] = __expf(lg[k] - m); ssum += es[k]; }
    float inv = __fdividef(validf, ssum);
    float gam[4];
#pragma unroll
    for (int k = 0; k < 4; k++) gam[k] = es[k] * inv;

    if (row < n) {
        g_z[row]            = z1v;
        g_z[MAXN + row]     = cd;
        g_z[2 * MAXN + row] = ed;
    }

    // ---------------- moments: warp reduce -> block reduce -> atomics ----------------
    float vals[41];
    {
        float p00 = z1v * z1v, p01 = z1v * cd, p02 = z1v * ed;
        float p11 = cd * cd,   p12 = cd * ed,  p22 = ed * ed;
        vals[40] = e2 * validf;
#pragma unroll
        for (int k = 0; k < 4; k++) {
            float gk = gam[k];
            vals[k]              = gk;
            vals[4 + k * 3 + 0]  = gk * z1v;
            vals[4 + k * 3 + 1]  = gk * cd;
            vals[4 + k * 3 + 2]  = gk * ed;
            vals[16 + k * 6 + 0] = gk * p00;
            vals[16 + k * 6 + 1] = gk * p01;
            vals[16 + k * 6 + 2] = gk * p02;
            vals[16 + k * 6 + 3] = gk * p11;
            vals[16 + k * 6 + 4] = gk * p12;
            vals[16 + k * 6 + 5] = gk * p22;
        }
    }
    const int wid = tid >> 5, lane = tid & 31;
#pragma unroll
    for (int q = 0; q < 41; q++) {
        float r = wsum(vals[q]);
        if (lane == 0) sRed[wid][q] = r;
    }
    __syncthreads();
    if (tid < 41) {
        float r = sRed[0][tid] + sRed[1][tid] + sRed[2][tid] + sRed[3][tid];
        atomicAdd(&g_acc[tid], (double)r);
    }
}

// Derive GMM parameters ONCE (k-parallel; moments divided in double, rest in float)
__global__ void finalize_kernel(int n) {
    int k = threadIdx.x;
    if (k < 4) {
        double gs = g_acc[k];
        double m0 = g_acc[4 + k * 3 + 0] / gs;
        double m1 = g_acc[4 + k * 3 + 1] / gs;
        double m2 = g_acc[4 + k * 3 + 2] / gs;
        float a = (float)(g_acc[16 + k * 6 + 0] / gs - m0 * m0);
        float b = (float)(g_acc[16 + k * 6 + 1] / gs - m0 * m1);
        float c = (float)(g_acc[16 + k * 6 + 2] / gs - m0 * m2);
        float d = (float)(g_acc[16 + k * 6 + 3] / gs - m1 * m1);
        float e = (float)(g_acc[16 + k * 6 + 4] / gs - m1 * m2);
        float f = (float)(g_acc[16 + k * 6 + 5] / gs - m2 * m2);
        float det = a * (d * f - e * e) - b * (b * f - c * e) + c * (b * e - c * d);
        float id = __fdividef(1.f, det);
        g_si[k * 6 + 0] = (d * f - e * e) * id;
        g_si[k * 6 + 1] = (c * e - b * f) * id;
        g_si[k * 6 + 2] = (b * e - c * d) * id;
        g_si[k * 6 + 3] = (a * f - c * c) * id;
        g_si[k * 6 + 4] = (b * c - a * e) * id;
        g_si[k * 6 + 5] = (a * d - b * b) * id;
        g_mu[k * 3 + 0] = (float)m0;
        g_mu[k * 3 + 1] = (float)m1;
        g_mu[k * 3 + 2] = (float)m2;
        const float TWO_PI3 = 248.05021344239853f;   // (2*pi)^3
        float phi = (float)(gs / (double)n);
        g_c[k] = 0.5f * logf(TWO_PI3 * det) - logf(phi);
        float l3 = __fdividef(1.f, a) + __fdividef(1.f, d) + __fdividef(1.f, f);
        atomicAdd(&g_loss3, 1e-4f * l3);
    }
}

// energy + (last block) loss
__global__ void __launch_bounds__(256) energy_kernel(float* __restrict__ out, int n, int has_loss) {
    __shared__ float sE[8];
    const int tid = threadIdx.x;

    float mu[12], si[24], cc[4];
#pragma unroll
    for (int q = 0; q < 12; q++) mu[q] = g_mu[q];
#pragma unroll
    for (int q = 0; q < 24; q++) si[q] = g_si[q];
#pragma unroll
    for (int q = 0; q < 4; q++)  cc[q] = g_c[q];

    int i = blockIdx.x * blockDim.x + tid;
    bool v = i < n;
    int ii = v ? i : 0;
    float z0 = g_z[ii], zc = g_z[MAXN + ii], ze = g_z[2 * MAXN + ii];
    float en = 0.f;
#pragma unroll
    for (int k = 0; k < 4; k++) {
        float a = z0 - mu[k * 3 + 0];
        float b = zc - mu[k * 3 + 1];
        float c = ze - mu[k * 3 + 2];
        float q = si[k * 6 + 0] * a * a + si[k * 6 + 3] * b * b + si[k * 6 + 5] * c * c
                + 2.f * (si[k * 6 + 1] * a * b + si[k * 6 + 2] * a * c + si[k * 6 + 4] * b * c);
        en += cc[k] + 0.5f * q;
    }
    if (v) out[i] = en;

    float r = wsum(v ? en : 0.f);
    const int wid = tid >> 5, lane = tid & 31;
    if (lane == 0) sE[wid] = r;
    __syncthreads();
    if (tid == 0) {
        float t = 0.f;
#pragma unroll
        for (int w = 0; w < 8; w++) t += sE[w];
        atomicAdd(&g_acc[41], (double)t);
        __threadfence();
        unsigned int old = atomicInc(&g_ticket, gridDim.x - 1);   // self-resetting
        if (old == gridDim.x - 1) {                                // last block
            __threadfence();
            if (has_loss) {
                double loss = g_acc[40] / (double)n + 0.01 * (g_acc[41] / (double)n)
                            + (double)g_loss3;
                out[n] = (float)loss;
            }
        }
    }
}

extern "C" void kernel_launch(void* const* d_in, const int* in_sizes, int n_in,
                              void* d_out, int out_size) {
    const float* x1  = (const float*)d_in[0];
    const float* ew1 = (const float*)d_in[1];
    const float* eb1 = (const float*)d_in[2];
    const float* ew2 = (const float*)d_in[3];
    const float* eb2 = (const float*)d_in[4];
    const float* ew3 = (const float*)d_in[5];
    const float* eb3 = (const float*)d_in[6];
    const float* dw1 = (const float*)d_in[7];
    const float* db1 = (const float*)d_in[8];
    const float* dw2 = (const float*)d_in[9];
    const float* db2 = (const float*)d_in[10];
    const float* dw3 = (const float*)d_in[11];
    const float* db3 = (const float*)d_in[12];
    const float* tw1 = (const float*)d_in[13];
    const float* tb1 = (const float*)d_in[14];
    const float* tw2 = (const float*)d_in[15];
    const float* tb2 = (const float*)d_in[16];

    int n = in_sizes[0] / 128;
    if (n > MAXN) n = MAXN;
    float* out = (float*)d_out;

    prep_kernel<<<1, 256>>>(dw3, db3);
    int blocks = (n + TPB - 1) / TPB;
    size_t dyn = 2 * BUFF * sizeof(float);
    fwd_kernel<<<blocks, TPB, dyn>>>(x1, ew1, eb1, ew2, eb2, ew3, eb3,
                                     dw1, db1, dw2, db2, dw3, db3,
                                     tw1, tb1, tw2, tb2, n);
    finalize_kernel<<<1, 32>>>(n);
    energy_kernel<<<(n + 255) / 256, 256>>>(out, n, out_size > n ? 1 : 0);
}